// round 11
// baseline (speedup 1.0000x reference)
#include <cuda_runtime.h>
#include <cstdint>
#include <math.h>

#define NBLOCKS   296            // 148 SMs * 2 CTAs (96KB smem each)
#define NTHREADS  256
#define NSTAGES   6
#define CHUNK     16384          // bytes per stage (1024 float4 = 256 rows)
#define CHUNK_V4  (CHUNK / 16)   // 1024

__device__ float        g_partials[NBLOCKS];
__device__ unsigned int g_ticket = 0;

__device__ __forceinline__ uint32_t smem_u32(const void* p) {
    uint32_t a;
    asm("{ .reg .u64 t; cvta.to.shared.u64 t, %1; cvt.u32.u64 %0, t; }"
        : "=r"(a) : "l"(p));
    return a;
}

__device__ __forceinline__ void mbar_init(uint32_t mbar, uint32_t count) {
    asm volatile("mbarrier.init.shared.b64 [%0], %1;" :: "r"(mbar), "r"(count) : "memory");
}
__device__ __forceinline__ void mbar_expect_tx(uint32_t mbar, uint32_t bytes) {
    asm volatile("mbarrier.arrive.expect_tx.shared.b64 _, [%0], %1;"
                 :: "r"(mbar), "r"(bytes) : "memory");
}
__device__ __forceinline__ void mbar_wait(uint32_t mbar, uint32_t parity) {
    asm volatile(
        "{\n\t"
        ".reg .pred P;\n\t"
        "WL_%=:\n\t"
        "mbarrier.try_wait.parity.acquire.cta.shared::cta.b64 P, [%0], %1, 0x989680;\n\t"
        "@P bra.uni WD_%=;\n\t"
        "bra.uni WL_%=;\n\t"
        "WD_%=:\n\t"
        "}" :: "r"(mbar), "r"(parity) : "memory");
}
__device__ __forceinline__ void bulk_ld(uint32_t dst_smem, const void* src,
                                        uint32_t bytes, uint32_t mbar) {
    asm volatile(
        "cp.async.bulk.shared::cta.global.mbarrier::complete_tx::bytes "
        "[%0], [%1], %2, [%3];"
        :: "r"(dst_smem), "l"(src), "r"(bytes), "r"(mbar) : "memory");
}

__device__ __forceinline__ float rsqrt_approx(float x) {
    float r;
    asm("rsqrt.approx.f32 %0, %1;" : "=f"(r) : "f"(x));
    return r;
}
// lanes 4j..4j+3 hold the 4 segments of one row (D=16); each lane returns
// its 0.25 share of (|row|-1)^2.
__device__ __forceinline__ float quad_loss(float s) {
    s += __shfl_xor_sync(0xFFFFFFFFu, s, 1);
    s += __shfl_xor_sync(0xFFFFFFFFu, s, 2);
    float r = s * rsqrt_approx(s) - 1.0f;
    return 0.25f * r * r;
}
__device__ __forceinline__ float sq4(float4 f) {
    return f.x * f.x + f.y * f.y + f.z * f.z + f.w * f.w;
}

__global__ void __launch_bounds__(NTHREADS)
loss_kernel(const char* __restrict__ y, unsigned int nchunks,
            float* __restrict__ out, float inv_scale) {
    extern __shared__ __align__(128) char smem[];
    const uint32_t sbase  = smem_u32(smem);
    const uint32_t mbar0  = sbase + NSTAGES * CHUNK;
    const int tid = threadIdx.x;

    // chunks for this CTA: c = bid + j*NBLOCKS, j = 0..nch-1
    const unsigned bid = blockIdx.x;
    const unsigned nch = (nchunks > bid) ? (nchunks - bid + NBLOCKS - 1) / NBLOCKS : 0;

    if (tid == 0) {
        #pragma unroll
        for (int s = 0; s < NSTAGES; s++)
            mbar_init(mbar0 + s * 8, 1);
    }
    __syncthreads();

    if (tid == 0) {
        unsigned pre = nch < NSTAGES ? nch : NSTAGES;
        for (unsigned j = 0; j < pre; j++) {
            mbar_expect_tx(mbar0 + j * 8, CHUNK);
            bulk_ld(sbase + j * CHUNK,
                    y + (size_t)(bid + j * NBLOCKS) * CHUNK,
                    CHUNK, mbar0 + j * 8);
        }
    }

    float acc = 0.0f;
    for (unsigned j = 0; j < nch; j++) {
        const unsigned s      = j % NSTAGES;
        const unsigned parity = (j / NSTAGES) & 1u;
        mbar_wait(mbar0 + s * 8, parity);

        const float4* stg = (const float4*)(smem + s * CHUNK);
        float4 f0 = stg[tid];
        float4 f1 = stg[tid + 256];
        float4 f2 = stg[tid + 512];
        float4 f3 = stg[tid + 768];
        acc += quad_loss(sq4(f0));
        acc += quad_loss(sq4(f1));
        acc += quad_loss(sq4(f2));
        acc += quad_loss(sq4(f3));

        __syncthreads();                       // all reads of stage s done
        unsigned jn = j + NSTAGES;
        if (tid == 0 && jn < nch) {
            mbar_expect_tx(mbar0 + s * 8, CHUNK);
            bulk_ld(sbase + s * CHUNK,
                    y + (size_t)(bid + jn * NBLOCKS) * CHUNK,
                    CHUNK, mbar0 + s * 8);
        }
    }

    // block reduction
    #pragma unroll
    for (int m = 16; m > 0; m >>= 1)
        acc += __shfl_xor_sync(0xFFFFFFFFu, acc, m);

    __shared__ float warp_sums[NTHREADS / 32];
    int wid = tid >> 5, lid = tid & 31;
    if (lid == 0) warp_sums[wid] = acc;
    __syncthreads();

    if (wid == 0) {
        float b = (lid < NTHREADS / 32) ? warp_sums[lid] : 0.0f;
        #pragma unroll
        for (int m = 4; m > 0; m >>= 1)
            b += __shfl_xor_sync(0xFFFFFFFFu, b, m);
        if (lid == 0)
            g_partials[blockIdx.x] = b;
    }

    // single-kernel fan-in
    __shared__ bool is_last;
    __threadfence();
    if (tid == 0) {
        unsigned int old = atomicAdd(&g_ticket, 1u);
        is_last = (old == (unsigned)gridDim.x - 1u);
    }
    __syncthreads();

    if (is_last) {
        float s = 0.0f;
        for (int i = tid; i < (int)gridDim.x; i += NTHREADS)
            s += g_partials[i];
        #pragma unroll
        for (int m = 16; m > 0; m >>= 1)
            s += __shfl_xor_sync(0xFFFFFFFFu, s, m);
        if (lid == 0) warp_sums[wid] = s;
        __syncthreads();
        if (wid == 0) {
            float b = (lid < NTHREADS / 32) ? warp_sums[lid] : 0.0f;
            #pragma unroll
            for (int m = 4; m > 0; m >>= 1)
                b += __shfl_xor_sync(0xFFFFFFFFu, b, m);
            if (lid == 0) {
                out[0]   = b * inv_scale;   // LAMBDA1 = 1.0
                g_ticket = 0;               // reset for next graph replay
            }
        }
    }
}

extern "C" void kernel_launch(void* const* d_in, const int* in_sizes, int n_in,
                              void* d_out, int out_size) {
    const char* y      = (const char*)d_in[0];
    size_t bytes       = (size_t)in_sizes[0] * 4;          // fp32
    unsigned nchunks   = (unsigned)(bytes / CHUNK);        // 16384 exact
    float inv_scale    = (float)(1.0 / (double)in_sizes[0]);

    static const int SMEM_TOTAL = NSTAGES * CHUNK + NSTAGES * 8;
    cudaFuncSetAttribute(loss_kernel,
                         cudaFuncAttributeMaxDynamicSharedMemorySize, SMEM_TOTAL);

    loss_kernel<<<NBLOCKS, NTHREADS, SMEM_TOTAL>>>(y, nchunks, (float*)d_out, inv_scale);
}

// round 14
// speedup vs baseline: 1.0478x; 1.0478x over previous
#include <cuda_runtime.h>
#include <math.h>

#define NBLOCKS  888             // 148 SMs * 6 blocks; regs ~36 (unconstrained) -> 6 resident
#define NTHREADS 256
#define UNROLL   8

__device__ float        g_partials[NBLOCKS];
__device__ unsigned int g_ticket = 0;

__device__ __forceinline__ float rsqrt_approx(float x) {
    float r;
    asm("rsqrt.approx.f32 %0, %1;" : "=f"(r) : "f"(x));
    return r;
}

// lanes 4j..4j+3 hold the 4 segments of one row; combine, then return this
// lane's share of (|row|-1)^2 (i.e. 0.25x in each of the 4 lanes).
__device__ __forceinline__ float quad_loss(float s, bool active) {
    s += __shfl_xor_sync(0xFFFFFFFFu, s, 1);
    s += __shfl_xor_sync(0xFFFFFFFFu, s, 2);
    float r = s * rsqrt_approx(s) - 1.0f;   // sqrt(s) - 1, one MUFU.RSQ
    return active ? 0.25f * r * r : 0.0f;
}

__device__ __forceinline__ float sq4(float4 f) {
    return f.x * f.x + f.y * f.y + f.z * f.z + f.w * f.w;
}

__global__ void __launch_bounds__(NTHREADS)
loss_kernel(const float4* __restrict__ y4, long long nvec,
            float* __restrict__ out, float inv_scale) {
    const long long tid = (long long)blockIdx.x * NTHREADS + threadIdx.x;
    const long long T   = (long long)NBLOCKS * NTHREADS;   // multiple of 4

    const long long kfull = nvec / (UNROLL * T);   // uniform trip count

    float acc = 0.0f;
    for (long long k = 0; k < kfull; k++) {
        long long v = tid + k * (UNROLL * T);
        float4 f[UNROLL];
        #pragma unroll
        for (int u = 0; u < UNROLL; u++)          // 8 front-batched LDG.128
            f[u] = __ldcs(&y4[v + (long long)u * T]);
        #pragma unroll
        for (int u = 0; u < UNROLL; u++)
            acc += quad_loss(sq4(f[u]), true);
    }

    // Predicated uniform tail (nvec % 4 == 0 -> quad-uniform activity)
    {
        long long base = kfull * (UNROLL * T);
        #pragma unroll
        for (int t = 0; t < UNROLL; t++) {
            long long v = base + (long long)t * T + tid;
            bool active = v < nvec;
            float s = active ? sq4(__ldcs(&y4[v])) : 0.0f;
            acc += quad_loss(s, active);
        }
    }

    // block reduction
    #pragma unroll
    for (int m = 16; m > 0; m >>= 1)
        acc += __shfl_xor_sync(0xFFFFFFFFu, acc, m);

    __shared__ float warp_sums[NTHREADS / 32];
    int wid = threadIdx.x >> 5;
    int lid = threadIdx.x & 31;
    if (lid == 0) warp_sums[wid] = acc;
    __syncthreads();

    if (wid == 0) {
        float b = (lid < NTHREADS / 32) ? warp_sums[lid] : 0.0f;
        #pragma unroll
        for (int m = 4; m > 0; m >>= 1)
            b += __shfl_xor_sync(0xFFFFFFFFu, b, m);
        if (lid == 0)
            g_partials[blockIdx.x] = b;
    }

    // single-kernel fan-in: last block reduces the partials
    __shared__ bool is_last;
    __threadfence();
    if (threadIdx.x == 0) {
        unsigned int old = atomicAdd(&g_ticket, 1u);
        is_last = (old == (unsigned)gridDim.x - 1u);
    }
    __syncthreads();

    if (is_last) {
        float s = 0.0f;
        for (int i = threadIdx.x; i < (int)gridDim.x; i += NTHREADS)
            s += g_partials[i];
        #pragma unroll
        for (int m = 16; m > 0; m >>= 1)
            s += __shfl_xor_sync(0xFFFFFFFFu, s, m);
        if (lid == 0) warp_sums[wid] = s;
        __syncthreads();
        if (wid == 0) {
            float b = (lid < NTHREADS / 32) ? warp_sums[lid] : 0.0f;
            #pragma unroll
            for (int m = 4; m > 0; m >>= 1)
                b += __shfl_xor_sync(0xFFFFFFFFu, b, m);
            if (lid == 0) {
                out[0]   = b * inv_scale;   // LAMBDA1 = 1.0
                g_ticket = 0;               // reset for next graph replay
            }
        }
    }
}

extern "C" void kernel_launch(void* const* d_in, const int* in_sizes, int n_in,
                              void* d_out, int out_size) {
    const float4* y4  = (const float4*)d_in[0];
    long long n_elems = (long long)in_sizes[0];   // N * D
    long long nvec    = n_elems / 4;
    float inv_scale   = (float)(1.0 / (double)n_elems);

    loss_kernel<<<NBLOCKS, NTHREADS>>>(y4, nvec, (float*)d_out, inv_scale);
}